// round 13
// baseline (speedup 1.0000x reference)
#include <cuda_runtime.h>
#include <cstdint>

// ---------------- problem constants ----------------
#define M_TOTAL 4096            // B*T
#define N_TOTAL 128             // leaves
#define K_TOTAL 16080           // in_features
#define SPLITS  7               // 64 M-tiles x 7 = 448 CTAs ~= 148 SMs * occ3
#define G16     1005            // K in 16-float granules (split boundaries)

// ---------------- tiling ----------------
#define MB 64                   // CTA M tile (occ-3 register budget)
#define KS 32                   // K floats per stage
#define ROWB 80                 // smem row stride bytes (32 fp16 + 16B pad)
#define A_TILE (MB * ROWB)                // 5120
#define B_TILE (128 * ROWB)               // 10240
#define STAGE_BYTES (A_TILE + B_TILE)     // 15360
#define SMEM_BYTES (2 * STAGE_BYTES)      // 30720 (double buffer, static)

// split-K partial accumulators (static scratch; device allocation is banned)
__device__ float g_part[(size_t)SPLITS * M_TOTAL * N_TOTAL];

__device__ __forceinline__ uint32_t pack_h2(float lo, float hi) {
    uint32_t d;
    asm("cvt.rn.f16x2.f32 %0, %1, %2;" : "=r"(d) : "f"(hi), "f"(lo));
    return d;
}
__device__ __forceinline__ void ldsm4(uint32_t* r, uint32_t addr) {
    asm volatile("ldmatrix.sync.aligned.m8n8.x4.shared.b16 {%0,%1,%2,%3}, [%4];"
                 : "=r"(r[0]), "=r"(r[1]), "=r"(r[2]), "=r"(r[3]) : "r"(addr));
}
__device__ __forceinline__ void mma_f16(float* c, const uint32_t* a,
                                        uint32_t b0, uint32_t b1) {
    asm volatile(
        "mma.sync.aligned.m16n8k16.row.col.f32.f16.f16.f32 "
        "{%0,%1,%2,%3}, {%4,%5,%6,%7}, {%8,%9}, {%0,%1,%2,%3};\n"
        : "+f"(c[0]), "+f"(c[1]), "+f"(c[2]), "+f"(c[3])
        : "r"(a[0]), "r"(a[1]), "r"(a[2]), "r"(a[3]), "r"(b0), "r"(b1));
}
__device__ __forceinline__ void sts128(uint32_t addr, uint32_t a, uint32_t b,
                                       uint32_t c, uint32_t d) {
    asm volatile("st.shared.v4.b32 [%0], {%1,%2,%3,%4};"
                 :: "r"(addr), "r"(a), "r"(b), "r"(c), "r"(d));
}

// =====================================================================
// GEMM partials: g_part[sp, M, N] = x[M, Kslice] . W[N, Kslice]^T
// fp16 HMMA m16n8k16. CTA tile 64x128, 8 warps as 2(M) x 4(N),
// warp tile 32x32. 3 CTAs/SM -> 24 warps/SM, 3 barrier domains.
// =====================================================================
__global__ __launch_bounds__(256, 3)
void gemm_f16_kernel(const float* __restrict__ x, const float* __restrict__ W) {
    __shared__ __align__(16) char smem[SMEM_BYTES];
    const uint32_t sbase = (uint32_t)__cvta_generic_to_shared(smem);

    const int tid  = threadIdx.x;
    const int lane = tid & 31;
    const int warp = tid >> 5;
    const int wm   = (warp >> 2) * 32;     // 2 warps in M
    const int wn   = (warp & 3) * 32;      // 4 warps in N
    const int g    = lane >> 2;
    const int tg   = lane & 3;

    const int m0 = blockIdx.x * MB;
    const int sp = blockIdx.y;
    const int g0 = (G16 * sp) / SPLITS;
    const int g1 = (G16 * (sp + 1)) / SPLITS;
    const int kbase = g0 * 16;
    const int ktot  = (g1 - g0) * 16;            // 2288 or 2304
    const int nst   = (ktot + KS - 1) / KS;      // 72
    const int ktail = ktot - (nst - 1) * KS;     // 16 or 32

    // ---- producer assignment
    // A: thread -> (row = tid>>2, 8-float chunk = tid&3)    [64 rows x 4 chunks]
    // B: thread -> (row = tid>>1, 16-float half = tid&1)    [128 rows x 2 halves]
    const int arow = tid >> 2, ac = tid & 3;
    const int brow = tid >> 1, bh = tid & 1;
    const float* gA = x + (size_t)(m0 + arow) * K_TOTAL + kbase + ac * 8;
    const float* gB = W + (size_t)brow * K_TOTAL + kbase + bh * 16;
    const uint32_t stA = sbase + (uint32_t)arow * ROWB + (uint32_t)ac * 16;
    const uint32_t stB = sbase + A_TILE + (uint32_t)brow * ROWB + (uint32_t)bh * 32;

    // ---- ldmatrix lane address (native m16n8k16 fragment order)
    const uint32_t loff =
        (uint32_t)(((lane & 7) + 8 * ((lane >> 3) & 1)) * ROWB + (lane >> 4) * 16);
    const uint32_t aBase = sbase + (uint32_t)wm * ROWB + loff;
    const uint32_t bBase = sbase + A_TILE + (uint32_t)wn * ROWB + loff;

    float acc[2][4][4];
    #pragma unroll
    for (int i = 0; i < 2; ++i)
        #pragma unroll
        for (int j = 0; j < 4; ++j)
            #pragma unroll
            for (int q = 0; q < 4; ++q) acc[i][j][q] = 0.0f;

    float4 ra[2], rb[4];

    auto load_regs = [&](int c) {
        const bool last16 = (c == nst - 1) && (ktail == 16);
        if (!(last16 && ac >= 2)) {
            const float4* pa = (const float4*)(gA + (size_t)c * KS);
            ra[0] = pa[0]; ra[1] = pa[1];
        }
        if (!(last16 && bh)) {
            const float4* pb = (const float4*)(gB + (size_t)c * KS);
            #pragma unroll
            for (int i = 0; i < 4; ++i) rb[i] = pb[i];
        }
    };
    auto cvt_sts = [&](int c) {
        const bool last16 = (c == nst - 1) && (ktail == 16);
        const uint32_t bo = (uint32_t)(c & 1) * STAGE_BYTES;
        if (!(last16 && ac >= 2)) {
            sts128(stA + bo,
                   pack_h2(ra[0].x, ra[0].y), pack_h2(ra[0].z, ra[0].w),
                   pack_h2(ra[1].x, ra[1].y), pack_h2(ra[1].z, ra[1].w));
        }
        if (!(last16 && bh)) {
            sts128(stB + bo,
                   pack_h2(rb[0].x, rb[0].y), pack_h2(rb[0].z, rb[0].w),
                   pack_h2(rb[1].x, rb[1].y), pack_h2(rb[1].z, rb[1].w));
            sts128(stB + bo + 16,
                   pack_h2(rb[2].x, rb[2].y), pack_h2(rb[2].z, rb[2].w),
                   pack_h2(rb[3].x, rb[3].y), pack_h2(rb[3].z, rb[3].w));
        }
    };

    load_regs(0);

    for (int c = 0; c < nst; ++c) {
        cvt_sts(c);
        __syncthreads();
        if (c + 1 < nst) load_regs(c + 1);   // LDG latency overlaps the MMA block

        const uint32_t bo = (uint32_t)(c & 1) * STAGE_BYTES;
        const int nks = ((c == nst - 1) ? ktail : KS) >> 4;   // 1 or 2 k16 steps

        #pragma unroll
        for (int ks = 0; ks < 2; ++ks) {
            if (ks >= nks) break;
            uint32_t a0[4], a1[4], bf[2][4];
            ldsm4(a0, aBase + bo + ks * 32u);
            ldsm4(a1, aBase + bo + ks * 32u + 16u * ROWB);
            #pragma unroll
            for (int jb = 0; jb < 2; ++jb)
                ldsm4(bf[jb], bBase + bo + ks * 32u + (uint32_t)jb * 16u * ROWB);
            #pragma unroll
            for (int jb = 0; jb < 2; ++jb) {
                mma_f16(acc[0][2 * jb],     a0, bf[jb][0], bf[jb][2]);
                mma_f16(acc[0][2 * jb + 1], a0, bf[jb][1], bf[jb][3]);
                mma_f16(acc[1][2 * jb],     a1, bf[jb][0], bf[jb][2]);
                mma_f16(acc[1][2 * jb + 1], a1, bf[jb][1], bf[jb][3]);
            }
        }
    }

    // ---- write split partials (warp tile 32x32 at (wm, wn))
    float* gp = g_part + (size_t)sp * (M_TOTAL * N_TOTAL) + (size_t)m0 * N_TOTAL;
    #pragma unroll
    for (int i = 0; i < 2; ++i) {
        #pragma unroll
        for (int j = 0; j < 4; ++j) {
            const int r    = wm + 16 * i + g;
            const int cIdx = wn + j * 8 + 2 * tg;
            *(float2*)(gp + (size_t)r * N_TOTAL + cIdx) =
                make_float2(acc[i][j][0], acc[i][j][1]);
            *(float2*)(gp + (size_t)(r + 8) * N_TOTAL + cIdx) =
                make_float2(acc[i][j][2], acc[i][j][3]);
        }
    }
}

// =====================================================================
// Epilogue: reduce split-K + bias + hardtanh, then softmax->Gini.
// |s|<=1 and |contrib|<1 ==> z in [-1,1]: no max-subtraction needed.
// =====================================================================
__global__ __launch_bounds__(256)
void epilogue_kernel(const float* __restrict__ bias,
                     const float* __restrict__ contrib,
                     float* __restrict__ out) {
    const int idx = blockIdx.x * 256 + threadIdx.x;   // 0 .. 4096*128-1
    const int l  = idx & 127;
    const int bt = idx >> 7;
    const int t  = bt & 63;

    float s = g_part[idx];
    #pragma unroll
    for (int sp = 1; sp < SPLITS; ++sp)
        s += g_part[(size_t)sp * (M_TOTAL * N_TOTAL) + idx];
    s += bias[l];
    s = fminf(1.0f, fmaxf(-1.0f, s));   // Hardtanh

    const float4* cp4 = (const float4*)(contrib + ((size_t)(t * 128 + l) << 4));
    float S = 0.0f, S2 = 0.0f;
    #pragma unroll
    for (int q = 0; q < 4; ++q) {
        float4 cv = cp4[q];
        float e0 = __expf(s * cv.x);
        float e1 = __expf(s * cv.y);
        float e2 = __expf(s * cv.z);
        float e3 = __expf(s * cv.w);
        S  += e0 + e1 + e2 + e3;
        S2 += e0 * e0 + e1 * e1 + e2 * e2 + e3 * e3;
    }
    const float gini = 16.0f - S2 / (S * S);

    out[idx] = s;
    out[(size_t)(M_TOTAL * N_TOTAL) + idx] = gini;
}

extern "C" void kernel_launch(void* const* d_in, const int* in_sizes, int n_in,
                              void* d_out, int out_size) {
    const float* x       = (const float*)d_in[0];  // [64,64,16080]
    const float* W       = (const float*)d_in[1];  // [128,16080]
    const float* b       = (const float*)d_in[2];  // [128]
    const float* contrib = (const float*)d_in[3];  // [64,128,16]
    float* out = (float*)d_out;

    gemm_f16_kernel<<<dim3(M_TOTAL / MB, SPLITS), 256>>>(x, W);
    epilogue_kernel<<<(M_TOTAL * N_TOTAL) / 256, 256>>>(b, contrib, out);
}

// round 14
// speedup vs baseline: 1.2491x; 1.2491x over previous
#include <cuda_runtime.h>
#include <cstdint>

// ---------------- problem constants ----------------
#define M_TOTAL 4096            // B*T
#define N_TOTAL 128             // leaves
#define K_TOTAL 16080           // in_features
#define SPLITS  9               // 32 M-tiles x 9 = 288 CTAs vs 296 slots (97.3%)
#define G16     1005            // K in 16-float granules (split boundaries)

// ---------------- tiling ----------------
#define KS 32                   // K per stage
#define ROWB 80                 // smem row stride bytes (32 fp16 = 64B + 16B pad)
#define TILE_BYTES (128 * ROWB)          // 10240 per matrix per stage
#define STAGE_BYTES (2 * TILE_BYTES)     // A then B
#define SMEM_BYTES (2 * STAGE_BYTES)     // 40960 (double buffer, static)

// split-K partial accumulators (static scratch; device allocation is banned)
__device__ float g_part[(size_t)SPLITS * M_TOTAL * N_TOTAL];

__device__ __forceinline__ uint32_t pack_h2(float lo, float hi) {
    uint32_t d;
    asm("cvt.rn.f16x2.f32 %0, %1, %2;" : "=r"(d) : "f"(hi), "f"(lo));
    return d;
}
__device__ __forceinline__ void ldsm4(uint32_t* r, uint32_t addr) {
    asm volatile("ldmatrix.sync.aligned.m8n8.x4.shared.b16 {%0,%1,%2,%3}, [%4];"
                 : "=r"(r[0]), "=r"(r[1]), "=r"(r[2]), "=r"(r[3]) : "r"(addr));
}
__device__ __forceinline__ void mma_f16(float* c, const uint32_t* a,
                                        uint32_t b0, uint32_t b1) {
    asm volatile(
        "mma.sync.aligned.m16n8k16.row.col.f32.f16.f16.f32 "
        "{%0,%1,%2,%3}, {%4,%5,%6,%7}, {%8,%9}, {%0,%1,%2,%3};\n"
        : "+f"(c[0]), "+f"(c[1]), "+f"(c[2]), "+f"(c[3])
        : "r"(a[0]), "r"(a[1]), "r"(a[2]), "r"(a[3]), "r"(b0), "r"(b1));
}
__device__ __forceinline__ void sts128(uint32_t addr, uint32_t a, uint32_t b,
                                       uint32_t c, uint32_t d) {
    asm volatile("st.shared.v4.b32 [%0], {%1,%2,%3,%4};"
                 :: "r"(addr), "r"(a), "r"(b), "r"(c), "r"(d));
}

// =====================================================================
// GEMM partials: g_part[sp, M, N] = x[M, Kslice] . W[N, Kslice]^T
// fp16 HMMA m16n8k16. CTA tile 128x128, 8 warps 4(M)x2(N), warp tile
// 32x64. 2 CTAs/SM (two interleaved barrier domains); SPLITS=9 fills
// 288 of 296 co-residency slots -> 97% wave balance.
// =====================================================================
__global__ __launch_bounds__(256, 2)
void gemm_f16_kernel(const float* __restrict__ x, const float* __restrict__ W) {
    __shared__ __align__(16) char smem[SMEM_BYTES];
    const uint32_t sbase = (uint32_t)__cvta_generic_to_shared(smem);

    const int tid  = threadIdx.x;
    const int lane = tid & 31;
    const int warp = tid >> 5;
    const int wm   = (warp >> 1) * 32;     // warp M origin (4 warps in M)
    const int wn   = (warp & 1) * 64;      // warp N origin (2 warps in N)
    const int g    = lane >> 2;
    const int tg   = lane & 3;

    const int m0 = blockIdx.x * 128;
    const int sp = blockIdx.y;
    const int g0 = (G16 * sp) / SPLITS;
    const int g1 = (G16 * (sp + 1)) / SPLITS;
    const int kbase = g0 * 16;
    const int ktot  = (g1 - g0) * 16;            // ~1776..1792
    const int nst   = (ktot + KS - 1) / KS;      // ~56
    const int ktail = ktot - (nst - 1) * KS;     // 16 or 32

    // ---- producer assignment: thread -> (row, 16-float half-row)
    const int prow = tid >> 1;
    const int ch   = tid & 1;
    const float* gA = x + (size_t)(m0 + prow) * K_TOTAL + kbase + ch * 16;
    const float* gB = W + (size_t)prow * K_TOTAL + kbase + ch * 16;
    const uint32_t stA = sbase + (uint32_t)prow * ROWB + (uint32_t)ch * 32;
    const uint32_t stB = stA + TILE_BYTES;

    // ---- ldmatrix lane address (native m16n8k16 fragment order)
    const uint32_t loff =
        (uint32_t)(((lane & 7) + 8 * ((lane >> 3) & 1)) * ROWB + (lane >> 4) * 16);
    const uint32_t aBase = sbase + (uint32_t)wm * ROWB + loff;
    const uint32_t bBase = sbase + TILE_BYTES + (uint32_t)wn * ROWB + loff;

    float acc[2][8][4];
    #pragma unroll
    for (int i = 0; i < 2; ++i)
        #pragma unroll
        for (int j = 0; j < 8; ++j)
            #pragma unroll
            for (int q = 0; q < 4; ++q) acc[i][j][q] = 0.0f;

    float4 ra[4], rb[4];

    auto load_regs = [&](int c) {
        const bool active = (ch == 0) || !(c == nst - 1 && ktail == 16);
        if (active) {
            const float4* pa = (const float4*)(gA + (size_t)c * KS);
            const float4* pb = (const float4*)(gB + (size_t)c * KS);
            #pragma unroll
            for (int i = 0; i < 4; ++i) { ra[i] = pa[i]; rb[i] = pb[i]; }
        }
    };
    auto cvt_sts = [&](int c) {
        const bool active = (ch == 0) || !(c == nst - 1 && ktail == 16);
        if (active) {
            const uint32_t bo = (uint32_t)(c & 1) * STAGE_BYTES;
            sts128(stA + bo,
                   pack_h2(ra[0].x, ra[0].y), pack_h2(ra[0].z, ra[0].w),
                   pack_h2(ra[1].x, ra[1].y), pack_h2(ra[1].z, ra[1].w));
            sts128(stA + bo + 16,
                   pack_h2(ra[2].x, ra[2].y), pack_h2(ra[2].z, ra[2].w),
                   pack_h2(ra[3].x, ra[3].y), pack_h2(ra[3].z, ra[3].w));
            sts128(stB + bo,
                   pack_h2(rb[0].x, rb[0].y), pack_h2(rb[0].z, rb[0].w),
                   pack_h2(rb[1].x, rb[1].y), pack_h2(rb[1].z, rb[1].w));
            sts128(stB + bo + 16,
                   pack_h2(rb[2].x, rb[2].y), pack_h2(rb[2].z, rb[2].w),
                   pack_h2(rb[3].x, rb[3].y), pack_h2(rb[3].z, rb[3].w));
        }
    };

    load_regs(0);

    for (int c = 0; c < nst; ++c) {
        cvt_sts(c);
        __syncthreads();
        if (c + 1 < nst) load_regs(c + 1);   // LDG latency overlaps the MMA block

        const uint32_t bo = (uint32_t)(c & 1) * STAGE_BYTES;
        const int nks = ((c == nst - 1) ? ktail : KS) >> 4;   // 1 or 2 k16 steps

        #pragma unroll
        for (int ks = 0; ks < 2; ++ks) {
            if (ks >= nks) break;
            uint32_t a0[4], a1[4], bf[4][4];
            ldsm4(a0, aBase + bo + ks * 32u);
            ldsm4(a1, aBase + bo + ks * 32u + 16u * ROWB);
            #pragma unroll
            for (int jb = 0; jb < 4; ++jb)
                ldsm4(bf[jb], bBase + bo + ks * 32u + (uint32_t)jb * 16u * ROWB);
            #pragma unroll
            for (int jb = 0; jb < 4; ++jb) {
                mma_f16(acc[0][2 * jb],     a0, bf[jb][0], bf[jb][2]);
                mma_f16(acc[0][2 * jb + 1], a0, bf[jb][1], bf[jb][3]);
                mma_f16(acc[1][2 * jb],     a1, bf[jb][0], bf[jb][2]);
                mma_f16(acc[1][2 * jb + 1], a1, bf[jb][1], bf[jb][3]);
            }
        }
    }

    // ---- write split partials
    float* gp = g_part + (size_t)sp * (M_TOTAL * N_TOTAL) + (size_t)m0 * N_TOTAL;
    #pragma unroll
    for (int i = 0; i < 2; ++i) {
        #pragma unroll
        for (int j = 0; j < 8; ++j) {
            const int r    = wm + 16 * i + g;
            const int cIdx = wn + j * 8 + 2 * tg;
            *(float2*)(gp + (size_t)r * N_TOTAL + cIdx) =
                make_float2(acc[i][j][0], acc[i][j][1]);
            *(float2*)(gp + (size_t)(r + 8) * N_TOTAL + cIdx) =
                make_float2(acc[i][j][2], acc[i][j][3]);
        }
    }
}

// =====================================================================
// Epilogue: reduce split-K + bias + hardtanh, then softmax->Gini.
// |s|<=1 and |contrib|<1 ==> z in [-1,1]: no max-subtraction needed.
// =====================================================================
__global__ __launch_bounds__(256)
void epilogue_kernel(const float* __restrict__ bias,
                     const float* __restrict__ contrib,
                     float* __restrict__ out) {
    const int idx = blockIdx.x * 256 + threadIdx.x;   // 0 .. 4096*128-1
    const int l  = idx & 127;
    const int bt = idx >> 7;
    const int t  = bt & 63;

    float s = g_part[idx];
    #pragma unroll
    for (int sp = 1; sp < SPLITS; ++sp)
        s += g_part[(size_t)sp * (M_TOTAL * N_TOTAL) + idx];
    s += bias[l];
    s = fminf(1.0f, fmaxf(-1.0f, s));   // Hardtanh

    const float4* cp4 = (const float4*)(contrib + ((size_t)(t * 128 + l) << 4));
    float S = 0.0f, S2 = 0.0f;
    #pragma unroll
    for (int q = 0; q < 4; ++q) {
        float4 cv = cp4[q];
        float e0 = __expf(s * cv.x);
        float e1 = __expf(s * cv.y);
        float e2 = __expf(s * cv.z);
        float e3 = __expf(s * cv.w);
        S  += e0 + e1 + e2 + e3;
        S2 += e0 * e0 + e1 * e1 + e2 * e2 + e3 * e3;
    }
    const float gini = 16.0f - S2 / (S * S);

    out[idx] = s;
    out[(size_t)(M_TOTAL * N_TOTAL) + idx] = gini;
}

extern "C" void kernel_launch(void* const* d_in, const int* in_sizes, int n_in,
                              void* d_out, int out_size) {
    const float* x       = (const float*)d_in[0];  // [64,64,16080]
    const float* W       = (const float*)d_in[1];  // [128,16080]
    const float* b       = (const float*)d_in[2];  // [128]
    const float* contrib = (const float*)d_in[3];  // [64,128,16]
    float* out = (float*)d_out;

    gemm_f16_kernel<<<dim3(M_TOTAL / 128, SPLITS), 256>>>(x, W);
    epilogue_kernel<<<(M_TOTAL * N_TOTAL) / 256, 256>>>(b, contrib, out);
}